// round 8
// baseline (speedup 1.0000x reference)
#include <cuda_runtime.h>
#include <cuda_bf16.h>
#include <cstdint>
#include <cstddef>

// Problem constants
#define BB   8
#define CC   62
#define GG   26
#define G3   17576
#define G2   676
#define NPT  32768
#define HH   1024
#define YSZ  (BB*3*NPT)

#define NB1 1099
#define NB2 69
#define NB3 5

// ---------------- scratch ----------------
__device__ float g_csum[BB * G3];
__device__ float g_bsum[BB * NB1];
__device__ int   g_counts[BB * G3];
__device__ int   g_offs[BB * G3];
__device__ int   g_sorted[BB * NPT];
__device__ __align__(16) __nv_bfloat16 g_w1hi[HH * 64];
__device__ __align__(16) __nv_bfloat16 g_w1lo[HH * 64];
__device__ float4 g_pack[HH];   // (b1, w2_0, w2_1, w2_2)

// ---------------- PTX helpers ----------------
__device__ __forceinline__ uint32_t smem_u32(const void* p) {
    uint32_t a;
    asm("{ .reg .u64 t; cvta.to.shared.u64 t, %1; cvt.u32.u64 %0, t; }" : "=r"(a) : "l"(p));
    return a;
}
__device__ __forceinline__ void cp_async16(uint32_t smem_dst, const void* gmem_src) {
    asm volatile("cp.async.ca.shared.global [%0], [%1], 16;" :: "r"(smem_dst), "l"(gmem_src));
}
__device__ __forceinline__ void cp_commit() { asm volatile("cp.async.commit_group;"); }
template <int N>
__device__ __forceinline__ void cp_wait() { asm volatile("cp.async.wait_group %0;" :: "n"(N)); }

__device__ __forceinline__ void ldsm_x4(uint32_t* r, uint32_t addr) {
    asm volatile("ldmatrix.sync.aligned.m8n8.x4.shared.b16 {%0,%1,%2,%3}, [%4];"
                 : "=r"(r[0]), "=r"(r[1]), "=r"(r[2]), "=r"(r[3]) : "r"(addr));
}
__device__ __forceinline__ void mma16816(float* d, const uint32_t* a, const uint32_t* b) {
    asm volatile(
        "mma.sync.aligned.m16n8k16.row.col.f32.bf16.bf16.f32 "
        "{%0,%1,%2,%3}, {%4,%5,%6,%7}, {%8,%9}, {%0,%1,%2,%3};"
        : "+f"(d[0]), "+f"(d[1]), "+f"(d[2]), "+f"(d[3])
        : "r"(a[0]), "r"(a[1]), "r"(a[2]), "r"(a[3]), "r"(b[0]), "r"(b[1]));
}

// ---------------- kernel: prep W1 split + pack ----------------
__global__ void k_prepw(const float* __restrict__ W1, const float* __restrict__ b1,
                        const float* __restrict__ W2) {
    int i = blockIdx.x * blockDim.x + threadIdx.x;
    if (i < HH * 64) {
        float w = W1[i];
        __nv_bfloat16 hi = __float2bfloat16(w);
        __nv_bfloat16 lo = __float2bfloat16(w - __bfloat162float(hi));
        g_w1hi[i] = hi;
        g_w1lo[i] = lo;
    }
    if (i < HH) g_pack[i] = make_float4(b1[i], W2[i], W2[HH + i], W2[2 * HH + i]);
}

// ---------------- kernel 1: XLA:CPU ReduceWindowRewriter-exact cumsum ----------------
__global__ __launch_bounds__(1024) void k_cumsum_rw(const float* __restrict__ dens) {
    __shared__ float T1[NB1];
    __shared__ float T2[NB2];
    __shared__ float T3[NB3];
    const int b = blockIdx.x;
    const int tid = threadIdx.x;
    const float* d = dens + (size_t)b * G3;

    {
        int4* cz = reinterpret_cast<int4*>(g_counts + b * G3);
        for (int i = tid; i < G3 / 4; i += 1024) cz[i] = make_int4(0, 0, 0, 0);
    }
    for (int j = tid; j < NB1; j += 1024) {
        const int s0 = j * 16, e0 = min(s0 + 16, G3);
        float s = 0.f;
        for (int i = s0; i < e0; ++i) s += d[i];
        T1[j] = s;
    }
    __syncthreads();
    if (tid < NB2) {
        const int s1 = tid * 16, e1 = min(s1 + 16, NB1);
        float s = 0.f;
        for (int i = s1; i < e1; ++i) s += T1[i];
        T2[tid] = s;
    }
    __syncthreads();
    if (tid == 0) {
        for (int j = 0; j < NB3; ++j) {
            const int s2 = j * 16, e2 = min(s2 + 16, NB2);
            float s = 0.f;
            for (int i = s2; i < e2; ++i) s += T2[i];
            T3[j] = s;
        }
        float s = 0.f;
        for (int j = 0; j < NB3; ++j) { s += T3[j]; T3[j] = s; }
        for (int j2 = 0; j2 < NB3; ++j2) {
            const float P = (j2 > 0) ? T3[j2 - 1] : 0.0f;
            float sr = 0.f;
            const int s2 = j2 * 16, e2 = min(j2 * 16 + 16, NB2);
            for (int i = s2; i < e2; ++i) { sr += T2[i]; T2[i] = sr + P; }
        }
    }
    __syncthreads();
    if (tid < NB2) {
        const float P = (tid > 0) ? T2[tid - 1] : 0.0f;
        float sr = 0.f;
        const int s1 = tid * 16, e1 = min(tid * 16 + 16, NB1);
        for (int i = s1; i < e1; ++i) { sr += T1[i]; T1[i] = sr + P; }
    }
    __syncthreads();
    float* cs = g_csum + (size_t)b * G3;
    for (int j = tid; j < NB1; j += 1024) {
        const float P = (j > 0) ? T1[j - 1] : 0.0f;
        float sr = 0.f;
        const int s0 = j * 16, e0 = min(j * 16 + 16, G3);
        float last = 0.f;
        for (int i = s0; i < e0; ++i) {
            sr += d[i];
            last = sr + P;
            cs[i] = last;
        }
        g_bsum[b * NB1 + j] = last;   // bit-equal to cs at block end
    }
}

// ---------------- kernel 2: sample -> histogram (hierarchical search) ----------------
__global__ void k_sample(const float* __restrict__ u) {
    int g = blockIdx.x * blockDim.x + threadIdx.x;
    if (g >= BB * NPT) return;
    int b = g >> 15;
    const float* bs = g_bsum + b * NB1;
    const float* cs = g_csum + (size_t)b * G3;
    float t = u[g] * bs[NB1 - 1];
    // coarse: first block j with bsum[j] > t
    int lo = 0, hi = NB1;
    while (lo < hi) {
        int mid = (lo + hi) >> 1;
        if (bs[mid] <= t) lo = mid + 1; else hi = mid;
    }
    int idx;
    if (lo >= NB1) {
        idx = G3 - 1;
    } else {
        int s = lo * 16;
        int e = min(s + 16, G3);
        while (s < e) {
            int mid = (s + e) >> 1;
            if (cs[mid] <= t) s = mid + 1; else e = mid;
        }
        idx = min(s, G3 - 1);
    }
    atomicAdd(&g_counts[b * G3 + idx], 1);
}

// ---------------- kernel 3a: offsets scan (8 CTAs) ----------------
#define BINS_PT 18
__global__ __launch_bounds__(1024) void k_scan() {
    const int b = blockIdx.x;
    const int* cnt = g_counts + b * G3;
    int* offs = g_offs + b * G3;
    __shared__ int wsum[32];
    const int tid = threadIdx.x;
    const int lane = tid & 31, wid = tid >> 5;
    const int base = tid * BINS_PT;

    int c[BINS_PT], pre[BINS_PT];
    int s = 0;
    #pragma unroll
    for (int r = 0; r < BINS_PT; ++r) {
        const int i = base + r;
        c[r] = (i < G3) ? cnt[i] : 0;
        pre[r] = s; s += c[r];
    }
    int x = s;
    #pragma unroll
    for (int d = 1; d < 32; d <<= 1) {
        int y = __shfl_up_sync(0xffffffffu, x, d);
        if (lane >= d) x += y;
    }
    if (lane == 31) wsum[wid] = x;
    __syncthreads();
    if (wid == 0) {
        int t = wsum[lane];
        #pragma unroll
        for (int d = 1; d < 32; d <<= 1) {
            int y = __shfl_up_sync(0xffffffffu, t, d);
            if (lane >= d) t += y;
        }
        wsum[lane] = t;
    }
    __syncthreads();
    const int excl = (x - s) + (wid ? wsum[wid - 1] : 0);
    #pragma unroll
    for (int r = 0; r < BINS_PT; ++r) {
        const int i = base + r;
        if (i < G3) offs[i] = excl + pre[r];
    }
}

// ---------------- kernel 3b: run-length emit (64 CTAs) ----------------
#define SLICE 2197   // G3/8
__global__ __launch_bounds__(256) void k_emit() {
    const int b = blockIdx.x >> 3;
    const int sl = blockIdx.x & 7;
    const int* cnt = g_counts + b * G3;
    const int* offs = g_offs + b * G3;
    int* srt = g_sorted + b * NPT;
    const int lo = sl * SLICE;
    const int hiB = min(lo + SLICE, G3);
    for (int i = lo + threadIdx.x; i < hiB; i += 256) {
        const int o = offs[i];
        const int c = cnt[i];
        for (int k = 0; k < c; ++k) srt[o + k] = i;
    }
}

// ---------------- kernel 4: HMMA fused MLP, 32 points/warp ----------------
// 512 thr / 16 warps / 512 points per CTA. Warp owns 2 m16 A-tiles (32 pts).
// W1 hi/lo streamed in 16 chunks of 64 h (cp.async double buffer).
#define VPITCHB 144
#define SM_VHI  0
#define SM_VLO  73728                  // 512*144
#define SM_W    147456
#define WHALF   9216                   // 64*144
#define WBUFSZ  18432
#define SM_PACK 184320                 // 1024 float4
#define SM_IDX  200704                 // 512 ints
#define SM_TOTAL (SM_IDX + 2048 + 64)

__global__ __launch_bounds__(512, 1) void k_mlp_mma(
    const float* __restrict__ x, const float* __restrict__ rnd,
    const float* __restrict__ b2, float* __restrict__ out)
{
    extern __shared__ char smem[];
    const uint32_t sbase = smem_u32(smem);
    const int tid = threadIdx.x;
    const int wid = tid >> 5;
    const int lane = tid & 31;
    const int b = blockIdx.y;
    const int j0 = blockIdx.x * 512;

    int* sIdx = (int*)(smem + SM_IDX);
    const float4* sPack = (const float4*)(smem + SM_PACK);
    float4* sPackW = (float4*)(smem + SM_PACK);

    // kick one 64-h chunk: 1024 cp16 (hi 512 + lo 512), 2 per thread
    #define KICKW(CH, BUFI) {                                                   \
        _Pragma("unroll")                                                       \
        for (int i = 0; i < 2; ++i) {                                           \
            int lin = i * 512 + tid;                                            \
            int m = lin >> 9;                                                   \
            int r = (lin >> 3) & 63;                                            \
            int sg = lin & 7;                                                   \
            const __nv_bfloat16* src =                                          \
                (m ? g_w1lo : g_w1hi) + ((CH) * 64 + r) * 64 + sg * 8;          \
            cp_async16(sbase + SM_W + (BUFI) * WBUFSZ + m * WHALF               \
                       + r * VPITCHB + sg * 16, src);                           \
        }                                                                       \
        cp_commit(); }

    KICKW(0, 0);
    KICKW(1, 1);

    sIdx[tid] = g_sorted[b * NPT + j0 + tid];
    sPackW[tid] = g_pack[tid];
    sPackW[tid + 512] = g_pack[tid + 512];
    __syncthreads();

    // gather V -> bf16 hi/lo (1 thread per point)
    {
        const int p = tid;
        const int gidx = sIdx[p];
        const float* xb = x + (size_t)b * CC * G3 + gidx;
        __nv_bfloat16* vhi = (__nv_bfloat16*)(smem + SM_VHI);
        __nv_bfloat16* vlo = (__nv_bfloat16*)(smem + SM_VLO);
        #pragma unroll 2
        for (int c = 0; c < CC; ++c) {
            float v = xb[(size_t)c * G3];
            __nv_bfloat16 hi = __float2bfloat16(v);
            __nv_bfloat16 lo = __float2bfloat16(v - __bfloat162float(hi));
            vhi[p * 72 + c] = hi;
            vlo[p * 72 + c] = lo;
        }
        #pragma unroll
        for (int c0 = 0; c0 < 2; ++c0) {
            float v = rnd[((size_t)b * 2 + c0) * NPT + j0 + p] * 2.0f - 1.0f;
            __nv_bfloat16 hi = __float2bfloat16(v);
            __nv_bfloat16 lo = __float2bfloat16(v - __bfloat162float(hi));
            vhi[p * 72 + 62 + c0] = hi;
            vlo[p * 72 + 62 + c0] = lo;
        }
    }
    cp_wait<1>();
    __syncthreads();

    // A fragments: 2 tiles x (hi/lo) x 16 regs, loaded once
    uint32_t ahi[2][16], alo[2][16];
    #pragma unroll
    for (int tile = 0; tile < 2; ++tile) {
        const uint32_t rowoff = (uint32_t)((wid * 32 + tile * 16 + (lane & 15)) * VPITCHB
                                           + ((lane >> 4) << 4));
        #pragma unroll
        for (int ks = 0; ks < 4; ++ks) {
            ldsm_x4(&ahi[tile][ks * 4], sbase + SM_VHI + rowoff + ks * 32);
            ldsm_x4(&alo[tile][ks * 4], sbase + SM_VLO + rowoff + ks * 32);
        }
    }

    float acc[2][6];
    #pragma unroll
    for (int t = 0; t < 2; ++t)
        #pragma unroll
        for (int q = 0; q < 6; ++q) acc[t][q] = 0.f;

    const uint32_t bladdr = (uint32_t)(((lane & 7) * VPITCHB) + ((lane >> 3) << 4));

    for (int ch = 0; ch < 16; ++ch) {
        const uint32_t wbuf = sbase + SM_W + (ch & 1) * WBUFSZ;

        #pragma unroll
        for (int t8 = 0; t8 < 8; ++t8) {
            uint32_t bh[8], bl[8];
            const uint32_t ba = wbuf + t8 * 8 * VPITCHB + bladdr;
            ldsm_x4(&bh[0], ba);
            ldsm_x4(&bh[4], ba + 64);
            ldsm_x4(&bl[0], ba + WHALF);
            ldsm_x4(&bl[4], ba + WHALF + 64);

            const int h0 = ch * 64 + t8 * 8 + ((lane & 3) << 1);
            const float4 pk0 = sPack[h0];
            const float4 pk1 = sPack[h0 + 1];

            #pragma unroll
            for (int tile = 0; tile < 2; ++tile) {
                float dhh[4] = {0.f, 0.f, 0.f, 0.f};
                float dhl[4] = {0.f, 0.f, 0.f, 0.f};
                float dlh[4] = {0.f, 0.f, 0.f, 0.f};
                #pragma unroll
                for (int ks = 0; ks < 4; ++ks) {
                    mma16816(dhh, &ahi[tile][ks * 4], &bh[ks * 2]);
                    mma16816(dhl, &ahi[tile][ks * 4], &bl[ks * 2]);
                    mma16816(dlh, &alo[tile][ks * 4], &bh[ks * 2]);
                }
                float s0 = fmaxf(dhh[0] + dhl[0] + dlh[0] + pk0.x, 0.f);
                float s1 = fmaxf(dhh[1] + dhl[1] + dlh[1] + pk1.x, 0.f);
                float s2 = fmaxf(dhh[2] + dhl[2] + dlh[2] + pk0.x, 0.f);
                float s3 = fmaxf(dhh[3] + dhl[3] + dlh[3] + pk1.x, 0.f);
                acc[tile][0] = fmaf(pk0.y, s0, fmaf(pk1.y, s1, acc[tile][0]));
                acc[tile][1] = fmaf(pk0.z, s0, fmaf(pk1.z, s1, acc[tile][1]));
                acc[tile][2] = fmaf(pk0.w, s0, fmaf(pk1.w, s1, acc[tile][2]));
                acc[tile][3] = fmaf(pk0.y, s2, fmaf(pk1.y, s3, acc[tile][3]));
                acc[tile][4] = fmaf(pk0.z, s2, fmaf(pk1.z, s3, acc[tile][4]));
                acc[tile][5] = fmaf(pk0.w, s2, fmaf(pk1.w, s3, acc[tile][5]));
            }
        }

        __syncthreads();
        if (ch < 14) {
            KICKW(ch + 2, ch & 1);
            cp_wait<1>();
        } else if (ch == 14) {
            cp_wait<0>();
        }
        __syncthreads();
    }

    // quad reduce
    #pragma unroll
    for (int t = 0; t < 2; ++t)
        #pragma unroll
        for (int q = 0; q < 6; ++q) {
            acc[t][q] += __shfl_xor_sync(0xffffffffu, acc[t][q], 1);
            acc[t][q] += __shfl_xor_sync(0xffffffffu, acc[t][q], 2);
        }

    if ((lane & 3) == 0) {
        const float bb0 = __ldg(&b2[0]);
        const float bb1 = __ldg(&b2[1]);
        const float bb2 = __ldg(&b2[2]);
        #pragma unroll
        for (int tile = 0; tile < 2; ++tile) {
            #pragma unroll
            for (int half = 0; half < 2; ++half) {
                const int p = wid * 32 + tile * 16 + (lane >> 2) + half * 8;
                float v0 = acc[tile][half * 3 + 0] + bb0;
                float v1 = acc[tile][half * 3 + 1] + bb1;
                float v2 = acc[tile][half * 3 + 2] + bb2;
                const float nrm = sqrtf(v0 * v0 + v1 * v1 + v2 * v2);
                const float rg = fmaxf(nrm - 0.06661733875264912f, 0.0f);
                const int gidx = sIdx[p];
                const int ix = gidx / G2;
                const int rem = gidx - ix * G2;
                const int iy = rem / GG;
                const int iz = rem - iy * GG;
                const float ox = ((float)ix + 0.5f) * 2.0f / 26.0f - 1.0f;
                const float oy = ((float)iy + 0.5f) * 2.0f / 26.0f - 1.0f;
                const float oz = ((float)iz + 0.5f) * 2.0f / 26.0f - 1.0f;
                const size_t j = (size_t)j0 + p;
                out[((size_t)b * 3 + 0) * NPT + j] = v0 + ox;
                out[((size_t)b * 3 + 1) * NPT + j] = v1 + oy;
                out[((size_t)b * 3 + 2) * NPT + j] = v2 + oz;
                out[(size_t)YSZ + (size_t)b * NPT + j] = rg;
            }
        }
    }
}

// ---------------- launch ----------------
extern "C" void kernel_launch(void* const* d_in, const int* in_sizes, int n_in,
                              void* d_out, int out_size) {
    const float* x    = (const float*)d_in[0];
    const float* dens = (const float*)d_in[1];
    const float* rnd  = (const float*)d_in[2];
    const float* u    = (const float*)d_in[3];
    const float* W1   = (const float*)d_in[4];
    const float* b1   = (const float*)d_in[5];
    const float* W2   = (const float*)d_in[6];
    const float* b2   = (const float*)d_in[7];
    float* out = (float*)d_out;

    cudaFuncSetAttribute(k_mlp_mma, cudaFuncAttributeMaxDynamicSharedMemorySize, SM_TOTAL);

    k_prepw<<<(HH * 64 + 255) / 256, 256>>>(W1, b1, W2);
    k_cumsum_rw<<<BB, 1024>>>(dens);
    k_sample<<<(BB * NPT + 255) / 256, 256>>>(u);
    k_scan<<<BB, 1024>>>();
    k_emit<<<BB * 8, 256>>>();
    dim3 grid(NPT / 512, BB);
    k_mlp_mma<<<grid, 512, SM_TOTAL>>>(x, rnd, b2, out);
}

// round 9
// speedup vs baseline: 1.0581x; 1.0581x over previous
#include <cuda_runtime.h>
#include <cuda_bf16.h>
#include <cstdint>
#include <cstddef>

// Problem constants
#define BB   8
#define CC   62
#define GG   26
#define G3   17576
#define G2   676
#define NPT  32768
#define HH   1024
#define YSZ  (BB*3*NPT)

#define NB1 1099
#define NB2 69
#define NB3 5

// ---------------- scratch ----------------
__device__ float g_csum[BB * G3];
__device__ float g_bsum[BB * NB1];
__device__ int   g_counts[BB * G3];
__device__ int   g_offs[BB * G3];
__device__ int   g_sorted[BB * NPT];
__device__ __align__(16) __nv_bfloat16 g_w1hi[HH * 64];
__device__ __align__(16) __nv_bfloat16 g_w1lo[HH * 64];
__device__ float4 g_pack[HH];   // (b1, w2_0, w2_1, w2_2)

// ---------------- PTX helpers ----------------
__device__ __forceinline__ uint32_t smem_u32(const void* p) {
    uint32_t a;
    asm("{ .reg .u64 t; cvta.to.shared.u64 t, %1; cvt.u32.u64 %0, t; }" : "=r"(a) : "l"(p));
    return a;
}
__device__ __forceinline__ void cp_async16(uint32_t smem_dst, const void* gmem_src) {
    asm volatile("cp.async.ca.shared.global [%0], [%1], 16;" :: "r"(smem_dst), "l"(gmem_src));
}
__device__ __forceinline__ void cp_commit() { asm volatile("cp.async.commit_group;"); }
template <int N>
__device__ __forceinline__ void cp_wait() { asm volatile("cp.async.wait_group %0;" :: "n"(N)); }

__device__ __forceinline__ void ldsm_x4(uint32_t* r, uint32_t addr) {
    asm volatile("ldmatrix.sync.aligned.m8n8.x4.shared.b16 {%0,%1,%2,%3}, [%4];"
                 : "=r"(r[0]), "=r"(r[1]), "=r"(r[2]), "=r"(r[3]) : "r"(addr));
}
__device__ __forceinline__ void mma16816(float* d, const uint32_t* a, const uint32_t* b) {
    asm volatile(
        "mma.sync.aligned.m16n8k16.row.col.f32.bf16.bf16.f32 "
        "{%0,%1,%2,%3}, {%4,%5,%6,%7}, {%8,%9}, {%0,%1,%2,%3};"
        : "+f"(d[0]), "+f"(d[1]), "+f"(d[2]), "+f"(d[3])
        : "r"(a[0]), "r"(a[1]), "r"(a[2]), "r"(a[3]), "r"(b[0]), "r"(b[1]));
}

// ---------------- kernel: prep W1 split + pack ----------------
__global__ void k_prepw(const float* __restrict__ W1, const float* __restrict__ b1,
                        const float* __restrict__ W2) {
    int i = blockIdx.x * blockDim.x + threadIdx.x;
    if (i < HH * 64) {
        float w = W1[i];
        __nv_bfloat16 hi = __float2bfloat16(w);
        __nv_bfloat16 lo = __float2bfloat16(w - __bfloat162float(hi));
        g_w1hi[i] = hi;
        g_w1lo[i] = lo;
    }
    if (i < HH) g_pack[i] = make_float4(b1[i], W2[i], W2[HH + i], W2[2 * HH + i]);
}

// ---------------- kernel 1: XLA:CPU ReduceWindowRewriter-exact cumsum ----------------
__global__ __launch_bounds__(1024) void k_cumsum_rw(const float* __restrict__ dens) {
    __shared__ float T1[NB1];
    __shared__ float T2[NB2];
    __shared__ float T3[NB3];
    const int b = blockIdx.x;
    const int tid = threadIdx.x;
    const float* d = dens + (size_t)b * G3;

    {
        int4* cz = reinterpret_cast<int4*>(g_counts + b * G3);
        for (int i = tid; i < G3 / 4; i += 1024) cz[i] = make_int4(0, 0, 0, 0);
    }
    for (int j = tid; j < NB1; j += 1024) {
        const int s0 = j * 16, e0 = min(s0 + 16, G3);
        float s = 0.f;
        for (int i = s0; i < e0; ++i) s += d[i];
        T1[j] = s;
    }
    __syncthreads();
    if (tid < NB2) {
        const int s1 = tid * 16, e1 = min(s1 + 16, NB1);
        float s = 0.f;
        for (int i = s1; i < e1; ++i) s += T1[i];
        T2[tid] = s;
    }
    __syncthreads();
    if (tid == 0) {
        for (int j = 0; j < NB3; ++j) {
            const int s2 = j * 16, e2 = min(s2 + 16, NB2);
            float s = 0.f;
            for (int i = s2; i < e2; ++i) s += T2[i];
            T3[j] = s;
        }
        float s = 0.f;
        for (int j = 0; j < NB3; ++j) { s += T3[j]; T3[j] = s; }
        for (int j2 = 0; j2 < NB3; ++j2) {
            const float P = (j2 > 0) ? T3[j2 - 1] : 0.0f;
            float sr = 0.f;
            const int s2 = j2 * 16, e2 = min(j2 * 16 + 16, NB2);
            for (int i = s2; i < e2; ++i) { sr += T2[i]; T2[i] = sr + P; }
        }
    }
    __syncthreads();
    if (tid < NB2) {
        const float P = (tid > 0) ? T2[tid - 1] : 0.0f;
        float sr = 0.f;
        const int s1 = tid * 16, e1 = min(tid * 16 + 16, NB1);
        for (int i = s1; i < e1; ++i) { sr += T1[i]; T1[i] = sr + P; }
    }
    __syncthreads();
    float* cs = g_csum + (size_t)b * G3;
    for (int j = tid; j < NB1; j += 1024) {
        const float P = (j > 0) ? T1[j - 1] : 0.0f;
        float sr = 0.f;
        const int s0 = j * 16, e0 = min(j * 16 + 16, G3);
        float last = 0.f;
        for (int i = s0; i < e0; ++i) {
            sr += d[i];
            last = sr + P;
            cs[i] = last;
        }
        g_bsum[b * NB1 + j] = last;   // bit-equal to cs at block end
    }
}

// ---------------- kernel 2: sample -> histogram (hierarchical search) ----------------
__global__ void k_sample(const float* __restrict__ u) {
    int g = blockIdx.x * blockDim.x + threadIdx.x;
    if (g >= BB * NPT) return;
    int b = g >> 15;
    const float* bs = g_bsum + b * NB1;
    const float* cs = g_csum + (size_t)b * G3;
    float t = u[g] * bs[NB1 - 1];
    int lo = 0, hi = NB1;
    while (lo < hi) {
        int mid = (lo + hi) >> 1;
        if (bs[mid] <= t) lo = mid + 1; else hi = mid;
    }
    int idx;
    if (lo >= NB1) {
        idx = G3 - 1;
    } else {
        int s = lo * 16;
        int e = min(s + 16, G3);
        while (s < e) {
            int mid = (s + e) >> 1;
            if (cs[mid] <= t) s = mid + 1; else e = mid;
        }
        idx = min(s, G3 - 1);
    }
    atomicAdd(&g_counts[b * G3 + idx], 1);
}

// ---------------- kernel 3a: offsets scan (8 CTAs) ----------------
#define BINS_PT 18
__global__ __launch_bounds__(1024) void k_scan() {
    const int b = blockIdx.x;
    const int* cnt = g_counts + b * G3;
    int* offs = g_offs + b * G3;
    __shared__ int wsum[32];
    const int tid = threadIdx.x;
    const int lane = tid & 31, wid = tid >> 5;
    const int base = tid * BINS_PT;

    int c[BINS_PT], pre[BINS_PT];
    int s = 0;
    #pragma unroll
    for (int r = 0; r < BINS_PT; ++r) {
        const int i = base + r;
        c[r] = (i < G3) ? cnt[i] : 0;
        pre[r] = s; s += c[r];
    }
    int x = s;
    #pragma unroll
    for (int d = 1; d < 32; d <<= 1) {
        int y = __shfl_up_sync(0xffffffffu, x, d);
        if (lane >= d) x += y;
    }
    if (lane == 31) wsum[wid] = x;
    __syncthreads();
    if (wid == 0) {
        int t = wsum[lane];
        #pragma unroll
        for (int d = 1; d < 32; d <<= 1) {
            int y = __shfl_up_sync(0xffffffffu, t, d);
            if (lane >= d) t += y;
        }
        wsum[lane] = t;
    }
    __syncthreads();
    const int excl = (x - s) + (wid ? wsum[wid - 1] : 0);
    #pragma unroll
    for (int r = 0; r < BINS_PT; ++r) {
        const int i = base + r;
        if (i < G3) offs[i] = excl + pre[r];
    }
}

// ---------------- kernel 3b: run-length emit (64 CTAs) ----------------
#define SLICE 2197   // G3/8
__global__ __launch_bounds__(256) void k_emit() {
    const int b = blockIdx.x >> 3;
    const int sl = blockIdx.x & 7;
    const int* cnt = g_counts + b * G3;
    const int* offs = g_offs + b * G3;
    int* srt = g_sorted + b * NPT;
    const int lo = sl * SLICE;
    const int hiB = min(lo + SLICE, G3);
    for (int i = lo + threadIdx.x; i < hiB; i += 256) {
        const int o = offs[i];
        const int c = cnt[i];
        for (int k = 0; k < c; ++k) srt[o + k] = i;
    }
}

// ---------------- kernel 4: HMMA fused MLP, 32 points/warp, chained accum ----------------
#define VPITCHB 144
#define SM_VHI  0
#define SM_VLO  73728                  // 512*144
#define SM_W    147456
#define WHALF   9216                   // 64*144
#define WBUFSZ  18432
#define SM_PACK 184320                 // 1024 float4
#define SM_IDX  200704                 // 512 ints
#define SM_TOTAL (SM_IDX + 2048 + 64)

__global__ __launch_bounds__(512, 1) void k_mlp_mma(
    const float* __restrict__ x, const float* __restrict__ rnd,
    const float* __restrict__ b2, float* __restrict__ out)
{
    extern __shared__ char smem[];
    const uint32_t sbase = smem_u32(smem);
    const int tid = threadIdx.x;
    const int wid = tid >> 5;
    const int lane = tid & 31;
    const int b = blockIdx.y;
    const int j0 = blockIdx.x * 512;

    int* sIdx = (int*)(smem + SM_IDX);
    const float4* sPack = (const float4*)(smem + SM_PACK);
    float4* sPackW = (float4*)(smem + SM_PACK);

    #define KICKW(CH, BUFI) {                                                   \
        _Pragma("unroll")                                                       \
        for (int i = 0; i < 2; ++i) {                                           \
            int lin = i * 512 + tid;                                            \
            int m = lin >> 9;                                                   \
            int r = (lin >> 3) & 63;                                            \
            int sg = lin & 7;                                                   \
            const __nv_bfloat16* src =                                          \
                (m ? g_w1lo : g_w1hi) + ((CH) * 64 + r) * 64 + sg * 8;          \
            cp_async16(sbase + SM_W + (BUFI) * WBUFSZ + m * WHALF               \
                       + r * VPITCHB + sg * 16, src);                           \
        }                                                                       \
        cp_commit(); }

    KICKW(0, 0);
    KICKW(1, 1);

    sIdx[tid] = g_sorted[b * NPT + j0 + tid];
    sPackW[tid] = g_pack[tid];
    sPackW[tid + 512] = g_pack[tid + 512];
    __syncthreads();

    // gather V -> bf16 hi/lo (1 thread per point)
    {
        const int p = tid;
        const int gidx = sIdx[p];
        const float* xb = x + (size_t)b * CC * G3 + gidx;
        __nv_bfloat16* vhi = (__nv_bfloat16*)(smem + SM_VHI);
        __nv_bfloat16* vlo = (__nv_bfloat16*)(smem + SM_VLO);
        #pragma unroll 2
        for (int c = 0; c < CC; ++c) {
            float v = xb[(size_t)c * G3];
            __nv_bfloat16 hi = __float2bfloat16(v);
            __nv_bfloat16 lo = __float2bfloat16(v - __bfloat162float(hi));
            vhi[p * 72 + c] = hi;
            vlo[p * 72 + c] = lo;
        }
        #pragma unroll
        for (int c0 = 0; c0 < 2; ++c0) {
            float v = rnd[((size_t)b * 2 + c0) * NPT + j0 + p] * 2.0f - 1.0f;
            __nv_bfloat16 hi = __float2bfloat16(v);
            __nv_bfloat16 lo = __float2bfloat16(v - __bfloat162float(hi));
            vhi[p * 72 + 62 + c0] = hi;
            vlo[p * 72 + 62 + c0] = lo;
        }
    }
    cp_wait<1>();
    __syncthreads();

    // A fragments: 2 tiles x (hi/lo) x 16 regs, loaded once
    uint32_t ahi[2][16], alo[2][16];
    #pragma unroll
    for (int tile = 0; tile < 2; ++tile) {
        const uint32_t rowoff = (uint32_t)((wid * 32 + tile * 16 + (lane & 15)) * VPITCHB
                                           + ((lane >> 4) << 4));
        #pragma unroll
        for (int ks = 0; ks < 4; ++ks) {
            ldsm_x4(&ahi[tile][ks * 4], sbase + SM_VHI + rowoff + ks * 32);
            ldsm_x4(&alo[tile][ks * 4], sbase + SM_VLO + rowoff + ks * 32);
        }
    }

    float acc[2][6];
    #pragma unroll
    for (int t = 0; t < 2; ++t)
        #pragma unroll
        for (int q = 0; q < 6; ++q) acc[t][q] = 0.f;

    const uint32_t bladdr = (uint32_t)(((lane & 7) * VPITCHB) + ((lane >> 3) << 4));

    for (int ch = 0; ch < 16; ++ch) {
        const uint32_t wbuf = sbase + SM_W + (ch & 1) * WBUFSZ;

        #pragma unroll
        for (int t8 = 0; t8 < 8; ++t8) {
            uint32_t bh[8], bl[8];
            const uint32_t ba = wbuf + t8 * 8 * VPITCHB + bladdr;
            ldsm_x4(&bh[0], ba);
            ldsm_x4(&bh[4], ba + 64);
            ldsm_x4(&bl[0], ba + WHALF);
            ldsm_x4(&bl[4], ba + WHALF + 64);

            const int h0 = ch * 64 + t8 * 8 + ((lane & 3) << 1);
            const float4 pk0 = sPack[h0];
            const float4 pk1 = sPack[h0 + 1];

            // two independent 12-deep mma chains (one per tile), bias in init
            float d0[4] = {pk0.x, pk1.x, pk0.x, pk1.x};
            float d1[4] = {pk0.x, pk1.x, pk0.x, pk1.x};
            #pragma unroll
            for (int ks = 0; ks < 4; ++ks) {
                mma16816(d0, &ahi[0][ks * 4], &bh[ks * 2]);
                mma16816(d1, &ahi[1][ks * 4], &bh[ks * 2]);
            }
            #pragma unroll
            for (int ks = 0; ks < 4; ++ks) {
                mma16816(d0, &ahi[0][ks * 4], &bl[ks * 2]);
                mma16816(d1, &ahi[1][ks * 4], &bl[ks * 2]);
            }
            #pragma unroll
            for (int ks = 0; ks < 4; ++ks) {
                mma16816(d0, &alo[0][ks * 4], &bh[ks * 2]);
                mma16816(d1, &alo[1][ks * 4], &bh[ks * 2]);
            }

            {
                float s0 = fmaxf(d0[0], 0.f), s1 = fmaxf(d0[1], 0.f);
                float s2 = fmaxf(d0[2], 0.f), s3 = fmaxf(d0[3], 0.f);
                acc[0][0] = fmaf(pk0.y, s0, fmaf(pk1.y, s1, acc[0][0]));
                acc[0][1] = fmaf(pk0.z, s0, fmaf(pk1.z, s1, acc[0][1]));
                acc[0][2] = fmaf(pk0.w, s0, fmaf(pk1.w, s1, acc[0][2]));
                acc[0][3] = fmaf(pk0.y, s2, fmaf(pk1.y, s3, acc[0][3]));
                acc[0][4] = fmaf(pk0.z, s2, fmaf(pk1.z, s3, acc[0][4]));
                acc[0][5] = fmaf(pk0.w, s2, fmaf(pk1.w, s3, acc[0][5]));
            }
            {
                float s0 = fmaxf(d1[0], 0.f), s1 = fmaxf(d1[1], 0.f);
                float s2 = fmaxf(d1[2], 0.f), s3 = fmaxf(d1[3], 0.f);
                acc[1][0] = fmaf(pk0.y, s0, fmaf(pk1.y, s1, acc[1][0]));
                acc[1][1] = fmaf(pk0.z, s0, fmaf(pk1.z, s1, acc[1][1]));
                acc[1][2] = fmaf(pk0.w, s0, fmaf(pk1.w, s1, acc[1][2]));
                acc[1][3] = fmaf(pk0.y, s2, fmaf(pk1.y, s3, acc[1][3]));
                acc[1][4] = fmaf(pk0.z, s2, fmaf(pk1.z, s3, acc[1][4]));
                acc[1][5] = fmaf(pk0.w, s2, fmaf(pk1.w, s3, acc[1][5]));
            }
        }

        __syncthreads();
        if (ch < 14) {
            KICKW(ch + 2, ch & 1);
            cp_wait<1>();
        } else if (ch == 14) {
            cp_wait<0>();
        }
        __syncthreads();
    }

    // quad reduce
    #pragma unroll
    for (int t = 0; t < 2; ++t)
        #pragma unroll
        for (int q = 0; q < 6; ++q) {
            acc[t][q] += __shfl_xor_sync(0xffffffffu, acc[t][q], 1);
            acc[t][q] += __shfl_xor_sync(0xffffffffu, acc[t][q], 2);
        }

    if ((lane & 3) == 0) {
        const float bb0 = __ldg(&b2[0]);
        const float bb1 = __ldg(&b2[1]);
        const float bb2 = __ldg(&b2[2]);
        #pragma unroll
        for (int tile = 0; tile < 2; ++tile) {
            #pragma unroll
            for (int half = 0; half < 2; ++half) {
                const int p = wid * 32 + tile * 16 + (lane >> 2) + half * 8;
                float v0 = acc[tile][half * 3 + 0] + bb0;
                float v1 = acc[tile][half * 3 + 1] + bb1;
                float v2 = acc[tile][half * 3 + 2] + bb2;
                const float nrm = sqrtf(v0 * v0 + v1 * v1 + v2 * v2);
                const float rg = fmaxf(nrm - 0.06661733875264912f, 0.0f);
                const int gidx = sIdx[p];
                const int ix = gidx / G2;
                const int rem = gidx - ix * G2;
                const int iy = rem / GG;
                const int iz = rem - iy * GG;
                const float ox = ((float)ix + 0.5f) * 2.0f / 26.0f - 1.0f;
                const float oy = ((float)iy + 0.5f) * 2.0f / 26.0f - 1.0f;
                const float oz = ((float)iz + 0.5f) * 2.0f / 26.0f - 1.0f;
                const size_t j = (size_t)j0 + p;
                out[((size_t)b * 3 + 0) * NPT + j] = v0 + ox;
                out[((size_t)b * 3 + 1) * NPT + j] = v1 + oy;
                out[((size_t)b * 3 + 2) * NPT + j] = v2 + oz;
                out[(size_t)YSZ + (size_t)b * NPT + j] = rg;
            }
        }
    }
}

// ---------------- launch ----------------
extern "C" void kernel_launch(void* const* d_in, const int* in_sizes, int n_in,
                              void* d_out, int out_size) {
    const float* x    = (const float*)d_in[0];
    const float* dens = (const float*)d_in[1];
    const float* rnd  = (const float*)d_in[2];
    const float* u    = (const float*)d_in[3];
    const float* W1   = (const float*)d_in[4];
    const float* b1   = (const float*)d_in[5];
    const float* W2   = (const float*)d_in[6];
    const float* b2   = (const float*)d_in[7];
    float* out = (float*)d_out;

    cudaFuncSetAttribute(k_mlp_mma, cudaFuncAttributeMaxDynamicSharedMemorySize, SM_TOTAL);

    k_prepw<<<(HH * 64 + 255) / 256, 256>>>(W1, b1, W2);
    k_cumsum_rw<<<BB, 1024>>>(dens);
    k_sample<<<(BB * NPT + 255) / 256, 256>>>(u);
    k_scan<<<BB, 1024>>>();
    k_emit<<<BB * 8, 256>>>();
    dim3 grid(NPT / 512, BB);
    k_mlp_mma<<<grid, 512, SM_TOTAL>>>(x, rnd, b2, out);
}

// round 10
// speedup vs baseline: 1.2210x; 1.1540x over previous
#include <cuda_runtime.h>
#include <cuda_fp16.h>
#include <cstdint>
#include <cstddef>

// Problem constants
#define BB   8
#define CC   62
#define GG   26
#define G3   17576
#define G2   676
#define NPT  32768
#define HH   1024
#define YSZ  (BB*3*NPT)

#define NB1 1099
#define NB2 69
#define NB3 5

// ---------------- scratch ----------------
__device__ float g_csum[BB * G3];
__device__ float g_bsum[BB * NB1];
__device__ int   g_counts[BB * G3];
__device__ int   g_offs[BB * G3];
__device__ int   g_sorted[BB * NPT];
__device__ __align__(16) __half g_w1hi[HH * 64];
__device__ __align__(16) __half g_w1lo[HH * 64];
__device__ float4 g_pack[HH];   // (b1, w2_0, w2_1, w2_2)

// ---------------- PTX helpers ----------------
__device__ __forceinline__ uint32_t smem_u32(const void* p) {
    uint32_t a;
    asm("{ .reg .u64 t; cvta.to.shared.u64 t, %1; cvt.u32.u64 %0, t; }" : "=r"(a) : "l"(p));
    return a;
}
__device__ __forceinline__ void cp_async16(uint32_t smem_dst, const void* gmem_src) {
    asm volatile("cp.async.ca.shared.global [%0], [%1], 16;" :: "r"(smem_dst), "l"(gmem_src));
}
__device__ __forceinline__ void cp_commit() { asm volatile("cp.async.commit_group;"); }
template <int N>
__device__ __forceinline__ void cp_wait() { asm volatile("cp.async.wait_group %0;" :: "n"(N)); }

__device__ __forceinline__ void ldsm_x4(uint32_t* r, uint32_t addr) {
    asm volatile("ldmatrix.sync.aligned.m8n8.x4.shared.b16 {%0,%1,%2,%3}, [%4];"
                 : "=r"(r[0]), "=r"(r[1]), "=r"(r[2]), "=r"(r[3]) : "r"(addr));
}
__device__ __forceinline__ void mma16816h(float* d, const uint32_t* a, const uint32_t* b) {
    asm volatile(
        "mma.sync.aligned.m16n8k16.row.col.f32.f16.f16.f32 "
        "{%0,%1,%2,%3}, {%4,%5,%6,%7}, {%8,%9}, {%0,%1,%2,%3};"
        : "+f"(d[0]), "+f"(d[1]), "+f"(d[2]), "+f"(d[3])
        : "r"(a[0]), "r"(a[1]), "r"(a[2]), "r"(a[3]), "r"(b[0]), "r"(b[1]));
}

// ---------------- kernel: prep W1 split + pack ----------------
__global__ void k_prepw(const float* __restrict__ W1, const float* __restrict__ b1,
                        const float* __restrict__ W2) {
    int i = blockIdx.x * blockDim.x + threadIdx.x;
    if (i < HH * 64) {
        float w = W1[i];
        __half hi = __float2half(w);
        __half lo = __float2half(w - __half2float(hi));
        g_w1hi[i] = hi;
        g_w1lo[i] = lo;
    }
    if (i < HH) g_pack[i] = make_float4(b1[i], W2[i], W2[HH + i], W2[2 * HH + i]);
}

// ---------------- kernel 1: XLA:CPU ReduceWindowRewriter-exact cumsum ----------------
#define CS_SMEM (G3 * 4)
__global__ __launch_bounds__(1024) void k_cumsum_rw(const float* __restrict__ dens) {
    extern __shared__ float sd[];         // G3 floats, cached density
    __shared__ float T1[NB1];
    __shared__ float T2[NB2];
    __shared__ float T3[NB3];
    const int b = blockIdx.x;
    const int tid = threadIdx.x;

    // cache dens (float4) + zero counts
    {
        const float4* src = reinterpret_cast<const float4*>(dens + (size_t)b * G3);
        float4* dst = reinterpret_cast<float4*>(sd);
        int4* cz = reinterpret_cast<int4*>(g_counts + b * G3);
        for (int i = tid; i < G3 / 4; i += 1024) {
            dst[i] = src[i];
            cz[i] = make_int4(0, 0, 0, 0);
        }
    }
    __syncthreads();
    for (int j = tid; j < NB1; j += 1024) {
        const int s0 = j * 16, e0 = min(s0 + 16, G3);
        float s = 0.f;
        for (int i = s0; i < e0; ++i) s += sd[i];
        T1[j] = s;
    }
    __syncthreads();
    if (tid < NB2) {
        const int s1 = tid * 16, e1 = min(s1 + 16, NB1);
        float s = 0.f;
        for (int i = s1; i < e1; ++i) s += T1[i];
        T2[tid] = s;
    }
    __syncthreads();
    if (tid == 0) {
        for (int j = 0; j < NB3; ++j) {
            const int s2 = j * 16, e2 = min(s2 + 16, NB2);
            float s = 0.f;
            for (int i = s2; i < e2; ++i) s += T2[i];
            T3[j] = s;
        }
        float s = 0.f;
        for (int j = 0; j < NB3; ++j) { s += T3[j]; T3[j] = s; }
        for (int j2 = 0; j2 < NB3; ++j2) {
            const float P = (j2 > 0) ? T3[j2 - 1] : 0.0f;
            float sr = 0.f;
            const int s2 = j2 * 16, e2 = min(j2 * 16 + 16, NB2);
            for (int i = s2; i < e2; ++i) { sr += T2[i]; T2[i] = sr + P; }
        }
    }
    __syncthreads();
    if (tid < NB2) {
        const float P = (tid > 0) ? T2[tid - 1] : 0.0f;
        float sr = 0.f;
        const int s1 = tid * 16, e1 = min(tid * 16 + 16, NB1);
        for (int i = s1; i < e1; ++i) { sr += T1[i]; T1[i] = sr + P; }
    }
    __syncthreads();
    float* cs = g_csum + (size_t)b * G3;
    for (int j = tid; j < NB1; j += 1024) {
        const float P = (j > 0) ? T1[j - 1] : 0.0f;
        float sr = 0.f;
        const int s0 = j * 16, e0 = min(j * 16 + 16, G3);
        float last = 0.f;
        for (int i = s0; i < e0; ++i) {
            sr += sd[i];
            last = sr + P;
            cs[i] = last;
        }
        g_bsum[b * NB1 + j] = last;   // bit-equal to cs at block end
    }
}

// ---------------- kernel 2: sample (smem coarse search) -> histogram ----------------
// 128 CTAs: 16 per batch, 256 thr, 2048 samples each. bsum cached in smem.
__global__ __launch_bounds__(256) void k_sample(const float* __restrict__ u) {
    __shared__ float sbs[NB1];
    const int b = blockIdx.x >> 4;
    const int sl = blockIdx.x & 15;
    for (int i = threadIdx.x; i < NB1; i += 256) sbs[i] = g_bsum[b * NB1 + i];
    __syncthreads();
    const float total = sbs[NB1 - 1];
    const float* cs = g_csum + (size_t)b * G3;
    const int base = sl * 2048;
    #pragma unroll
    for (int r = 0; r < 8; ++r) {
        const int n = base + r * 256 + threadIdx.x;
        float t = u[b * NPT + n] * total;
        int lo = 0, hi = NB1;
        while (lo < hi) {
            int mid = (lo + hi) >> 1;
            if (sbs[mid] <= t) lo = mid + 1; else hi = mid;
        }
        int idx;
        if (lo >= NB1) {
            idx = G3 - 1;
        } else {
            int s = lo * 16;
            int e = min(s + 16, G3);
            while (s < e) {
                int mid = (s + e) >> 1;
                if (cs[mid] <= t) s = mid + 1; else e = mid;
            }
            idx = min(s, G3 - 1);
        }
        atomicAdd(&g_counts[b * G3 + idx], 1);
    }
}

// ---------------- kernel 3a: offsets scan (8 CTAs) ----------------
#define BINS_PT 18
__global__ __launch_bounds__(1024) void k_scan() {
    const int b = blockIdx.x;
    const int* cnt = g_counts + b * G3;
    int* offs = g_offs + b * G3;
    __shared__ int wsum[32];
    const int tid = threadIdx.x;
    const int lane = tid & 31, wid = tid >> 5;
    const int base = tid * BINS_PT;

    int c[BINS_PT], pre[BINS_PT];
    int s = 0;
    #pragma unroll
    for (int r = 0; r < BINS_PT; ++r) {
        const int i = base + r;
        c[r] = (i < G3) ? cnt[i] : 0;
        pre[r] = s; s += c[r];
    }
    int x = s;
    #pragma unroll
    for (int d = 1; d < 32; d <<= 1) {
        int y = __shfl_up_sync(0xffffffffu, x, d);
        if (lane >= d) x += y;
    }
    if (lane == 31) wsum[wid] = x;
    __syncthreads();
    if (wid == 0) {
        int t = wsum[lane];
        #pragma unroll
        for (int d = 1; d < 32; d <<= 1) {
            int y = __shfl_up_sync(0xffffffffu, t, d);
            if (lane >= d) t += y;
        }
        wsum[lane] = t;
    }
    __syncthreads();
    const int excl = (x - s) + (wid ? wsum[wid - 1] : 0);
    #pragma unroll
    for (int r = 0; r < BINS_PT; ++r) {
        const int i = base + r;
        if (i < G3) offs[i] = excl + pre[r];
    }
}

// ---------------- kernel 3b: run-length emit (64 CTAs) ----------------
#define SLICE 2197   // G3/8
__global__ __launch_bounds__(256) void k_emit() {
    const int b = blockIdx.x >> 3;
    const int sl = blockIdx.x & 7;
    const int* cnt = g_counts + b * G3;
    const int* offs = g_offs + b * G3;
    int* srt = g_sorted + b * NPT;
    const int lo = sl * SLICE;
    const int hiB = min(lo + SLICE, G3);
    for (int i = lo + threadIdx.x; i < hiB; i += 256) {
        const int o = offs[i];
        const int c = cnt[i];
        for (int k = 0; k < c; ++k) srt[o + k] = i;
    }
}

// ---------------- kernel 4: fp16 HMMA fused MLP (2-product split) ----------------
// out ~= A_hi(fp16) x (W_hi + W_lo)(fp16): A-side residual dropped (err ~1.5e-4 rel).
// 512 thr / 16 warps / 512 points. Warp: 2 m16 A-tiles. W streamed 16 x 64-h chunks.
#define VPITCHB 144                    // 72 halves (64 used + pad)
#define SM_VHI  0
#define SM_W    73728                  // 512*144
#define WHALF   9216                   // 64*144
#define WBUFSZ  18432
#define SM_PACK 110592                 // 1024 float4
#define SM_IDX  126976                 // 512 ints
#define SM_TOTAL (SM_IDX + 2048 + 64)

__global__ __launch_bounds__(512, 1) void k_mlp_mma(
    const float* __restrict__ x, const float* __restrict__ rnd,
    const float* __restrict__ b2, float* __restrict__ out)
{
    extern __shared__ char smem[];
    const uint32_t sbase = smem_u32(smem);
    const int tid = threadIdx.x;
    const int wid = tid >> 5;
    const int lane = tid & 31;
    const int b = blockIdx.y;
    const int j0 = blockIdx.x * 512;

    int* sIdx = (int*)(smem + SM_IDX);
    const float4* sPack = (const float4*)(smem + SM_PACK);
    float4* sPackW = (float4*)(smem + SM_PACK);

    #define KICKW(CH, BUFI) {                                                   \
        _Pragma("unroll")                                                       \
        for (int i = 0; i < 2; ++i) {                                           \
            int lin = i * 512 + tid;                                            \
            int m = lin >> 9;                                                   \
            int r = (lin >> 3) & 63;                                            \
            int sg = lin & 7;                                                   \
            const __half* src =                                                 \
                (m ? g_w1lo : g_w1hi) + ((CH) * 64 + r) * 64 + sg * 8;          \
            cp_async16(sbase + SM_W + (BUFI) * WBUFSZ + m * WHALF               \
                       + r * VPITCHB + sg * 16, src);                           \
        }                                                                       \
        cp_commit(); }

    KICKW(0, 0);
    KICKW(1, 1);

    sIdx[tid] = g_sorted[b * NPT + j0 + tid];
    sPackW[tid] = g_pack[tid];
    sPackW[tid + 512] = g_pack[tid + 512];
    __syncthreads();

    // gather V -> fp16 smem (1 thread per point)
    {
        const int p = tid;
        const int gidx = sIdx[p];
        const float* xb = x + (size_t)b * CC * G3 + gidx;
        __half* vhi = (__half*)(smem + SM_VHI);
        #pragma unroll 2
        for (int c = 0; c < CC; ++c)
            vhi[p * 72 + c] = __float2half(xb[(size_t)c * G3]);
        #pragma unroll
        for (int c0 = 0; c0 < 2; ++c0)
            vhi[p * 72 + 62 + c0] =
                __float2half(rnd[((size_t)b * 2 + c0) * NPT + j0 + p] * 2.0f - 1.0f);
    }
    cp_wait<1>();
    __syncthreads();

    // A fragments: 2 tiles x 16 regs, loaded once
    uint32_t ahi[2][16];
    #pragma unroll
    for (int tile = 0; tile < 2; ++tile) {
        const uint32_t rowoff = (uint32_t)((wid * 32 + tile * 16 + (lane & 15)) * VPITCHB
                                           + ((lane >> 4) << 4));
        #pragma unroll
        for (int ks = 0; ks < 4; ++ks)
            ldsm_x4(&ahi[tile][ks * 4], sbase + SM_VHI + rowoff + ks * 32);
    }

    float acc[2][6];
    #pragma unroll
    for (int t = 0; t < 2; ++t)
        #pragma unroll
        for (int q = 0; q < 6; ++q) acc[t][q] = 0.f;

    const uint32_t bladdr = (uint32_t)(((lane & 7) * VPITCHB) + ((lane >> 3) << 4));

    for (int ch = 0; ch < 16; ++ch) {
        const uint32_t wbuf = sbase + SM_W + (ch & 1) * WBUFSZ;

        #pragma unroll
        for (int t8 = 0; t8 < 8; ++t8) {
            uint32_t bh[8], bl[8];
            const uint32_t ba = wbuf + t8 * 8 * VPITCHB + bladdr;
            ldsm_x4(&bh[0], ba);
            ldsm_x4(&bh[4], ba + 64);
            ldsm_x4(&bl[0], ba + WHALF);
            ldsm_x4(&bl[4], ba + WHALF + 64);

            const int h0 = ch * 64 + t8 * 8 + ((lane & 3) << 1);
            const float4 pk0 = sPack[h0];
            const float4 pk1 = sPack[h0 + 1];

            // two independent 8-deep mma chains, bias in init
            float d0[4] = {pk0.x, pk1.x, pk0.x, pk1.x};
            float d1[4] = {pk0.x, pk1.x, pk0.x, pk1.x};
            #pragma unroll
            for (int ks = 0; ks < 4; ++ks) {
                mma16816h(d0, &ahi[0][ks * 4], &bh[ks * 2]);
                mma16816h(d1, &ahi[1][ks * 4], &bh[ks * 2]);
            }
            #pragma unroll
            for (int ks = 0; ks < 4; ++ks) {
                mma16816h(d0, &ahi[0][ks * 4], &bl[ks * 2]);
                mma16816h(d1, &ahi[1][ks * 4], &bl[ks * 2]);
            }

            {
                float s0 = fmaxf(d0[0], 0.f), s1 = fmaxf(d0[1], 0.f);
                float s2 = fmaxf(d0[2], 0.f), s3 = fmaxf(d0[3], 0.f);
                acc[0][0] = fmaf(pk0.y, s0, fmaf(pk1.y, s1, acc[0][0]));
                acc[0][1] = fmaf(pk0.z, s0, fmaf(pk1.z, s1, acc[0][1]));
                acc[0][2] = fmaf(pk0.w, s0, fmaf(pk1.w, s1, acc[0][2]));
                acc[0][3] = fmaf(pk0.y, s2, fmaf(pk1.y, s3, acc[0][3]));
                acc[0][4] = fmaf(pk0.z, s2, fmaf(pk1.z, s3, acc[0][4]));
                acc[0][5] = fmaf(pk0.w, s2, fmaf(pk1.w, s3, acc[0][5]));
            }
            {
                float s0 = fmaxf(d1[0], 0.f), s1 = fmaxf(d1[1], 0.f);
                float s2 = fmaxf(d1[2], 0.f), s3 = fmaxf(d1[3], 0.f);
                acc[1][0] = fmaf(pk0.y, s0, fmaf(pk1.y, s1, acc[1][0]));
                acc[1][1] = fmaf(pk0.z, s0, fmaf(pk1.z, s1, acc[1][1]));
                acc[1][2] = fmaf(pk0.w, s0, fmaf(pk1.w, s1, acc[1][2]));
                acc[1][3] = fmaf(pk0.y, s2, fmaf(pk1.y, s3, acc[1][3]));
                acc[1][4] = fmaf(pk0.z, s2, fmaf(pk1.z, s3, acc[1][4]));
                acc[1][5] = fmaf(pk0.w, s2, fmaf(pk1.w, s3, acc[1][5]));
            }
        }

        __syncthreads();
        if (ch < 14) {
            KICKW(ch + 2, ch & 1);
            cp_wait<1>();
        } else if (ch == 14) {
            cp_wait<0>();
        }
        __syncthreads();
    }

    // quad reduce
    #pragma unroll
    for (int t = 0; t < 2; ++t)
        #pragma unroll
        for (int q = 0; q < 6; ++q) {
            acc[t][q] += __shfl_xor_sync(0xffffffffu, acc[t][q], 1);
            acc[t][q] += __shfl_xor_sync(0xffffffffu, acc[t][q], 2);
        }

    if ((lane & 3) == 0) {
        const float bb0 = __ldg(&b2[0]);
        const float bb1 = __ldg(&b2[1]);
        const float bb2 = __ldg(&b2[2]);
        #pragma unroll
        for (int tile = 0; tile < 2; ++tile) {
            #pragma unroll
            for (int half = 0; half < 2; ++half) {
                const int p = wid * 32 + tile * 16 + (lane >> 2) + half * 8;
                float v0 = acc[tile][half * 3 + 0] + bb0;
                float v1 = acc[tile][half * 3 + 1] + bb1;
                float v2 = acc[tile][half * 3 + 2] + bb2;
                const float nrm = sqrtf(v0 * v0 + v1 * v1 + v2 * v2);
                const float rg = fmaxf(nrm - 0.06661733875264912f, 0.0f);
                const int gidx = sIdx[p];
                const int ix = gidx / G2;
                const int rem = gidx - ix * G2;
                const int iy = rem / GG;
                const int iz = rem - iy * GG;
                const float ox = ((float)ix + 0.5f) * 2.0f / 26.0f - 1.0f;
                const float oy = ((float)iy + 0.5f) * 2.0f / 26.0f - 1.0f;
                const float oz = ((float)iz + 0.5f) * 2.0f / 26.0f - 1.0f;
                const size_t j = (size_t)j0 + p;
                out[((size_t)b * 3 + 0) * NPT + j] = v0 + ox;
                out[((size_t)b * 3 + 1) * NPT + j] = v1 + oy;
                out[((size_t)b * 3 + 2) * NPT + j] = v2 + oz;
                out[(size_t)YSZ + (size_t)b * NPT + j] = rg;
            }
        }
    }
}

// ---------------- launch ----------------
extern "C" void kernel_launch(void* const* d_in, const int* in_sizes, int n_in,
                              void* d_out, int out_size) {
    const float* x    = (const float*)d_in[0];
    const float* dens = (const float*)d_in[1];
    const float* rnd  = (const float*)d_in[2];
    const float* u    = (const float*)d_in[3];
    const float* W1   = (const float*)d_in[4];
    const float* b1   = (const float*)d_in[5];
    const float* W2   = (const float*)d_in[6];
    const float* b2   = (const float*)d_in[7];
    float* out = (float*)d_out;

    cudaFuncSetAttribute(k_cumsum_rw, cudaFuncAttributeMaxDynamicSharedMemorySize, CS_SMEM);
    cudaFuncSetAttribute(k_mlp_mma, cudaFuncAttributeMaxDynamicSharedMemorySize, SM_TOTAL);

    k_prepw<<<(HH * 64 + 255) / 256, 256>>>(W1, b1, W2);
    k_cumsum_rw<<<BB, 1024, CS_SMEM>>>(dens);
    k_sample<<<BB * 16, 256>>>(u);
    k_scan<<<BB, 1024>>>();
    k_emit<<<BB * 8, 256>>>();
    dim3 grid(NPT / 512, BB);
    k_mlp_mma<<<grid, 512, SM_TOTAL>>>(x, rnd, b2, out);
}